// round 15
// baseline (speedup 1.0000x reference)
#include <cuda_runtime.h>
#include <math.h>

#define NPTS 131072
#define MSEG 4096
#define CCH  32
#define MIDD 16
#define KNB  6
#define ACCW 36
#define RREP 8
#define BN_EPS 1e-5f

// ---------------- f32x2 helpers (prep kernel) ----------------
__device__ __forceinline__ unsigned long long pk2(float lo, float hi) {
    unsigned long long r;
    asm("mov.b64 %0, {%1,%2};" : "=l"(r) : "f"(lo), "f"(hi));
    return r;
}
__device__ __forceinline__ void upk2(unsigned long long v, float& lo, float& hi) {
    asm("mov.b64 {%0,%1}, %2;" : "=f"(lo), "=f"(hi) : "l"(v));
}
__device__ __forceinline__ unsigned long long fma2(unsigned long long a, unsigned long long b,
                                                   unsigned long long c) {
    unsigned long long d;
    asm("fma.rn.f32x2 %0, %1, %2, %3;" : "=l"(d) : "l"(a), "l"(b), "l"(c));
    return d;
}

// ---------------- static device scratch ----------------
__device__ __align__(256) float g_sph[MSEG * 2 * MIDD];   // [m][0..15]=af*sphf, [m][16..31]=ax*sphx
__device__ __align__(256) float g_acc[RREP][MSEG * ACCW];
// pair-row layout: row r = 2n+path. planes 0..3 = V, 4..7 = B
__device__ __align__(256) float4 g_pv[8][2 * NPTS];
__device__ __align__(256) float  g_pb[2 * NPTS];

struct Prm {
    float O[2 * MIDD * MIDD];    // [q*256 + i*16 + j]: half-Gram, j<i doubled, j==i diag, j>i ZERO
    float g2[2 * MIDD];          // [q*16 + i] = 2 * W2^T b2
    float c[2];                  // ||b2||^2 per path
};
__device__ Prm g_prm;

// ---------------- setup ----------------
__global__ void setup_kernel(const float* __restrict__ wf2w, const float* __restrict__ wf2b,
                             const float* __restrict__ wx2w, const float* __restrict__ wx2b) {
    int t = threadIdx.x;            // 256
    int i = t >> 4, j = t & 15;
    float sf = 0.f, sx = 0.f;
#pragma unroll
    for (int c = 0; c < CCH; c++) {
        sf += wf2w[c * MIDD + i] * wf2w[c * MIDD + j];
        sx += wx2w[c * MIDD + i] * wx2w[c * MIDD + j];
    }
    g_prm.O[t]       = (j < i) ? 2.f * sf : (j == i ? sf : 0.f);
    g_prm.O[256 + t] = (j < i) ? 2.f * sx : (j == i ? sx : 0.f);
    if (t < MIDD) {
        float s1 = 0.f, s2 = 0.f;
#pragma unroll
        for (int c = 0; c < CCH; c++) {
            s1 += wf2w[c * MIDD + t] * wf2b[c];
            s2 += wx2w[c * MIDD + t] * wx2b[c];
        }
        g_prm.g2[t]        = 2.f * s1;
        g_prm.g2[MIDD + t] = 2.f * s2;
    } else if (t == 32) {
        float s = 0.f;
#pragma unroll
        for (int c = 0; c < CCH; c++) s += wf2b[c] * wf2b[c];
        g_prm.c[0] = s;
    } else if (t == 33) {
        float s = 0.f;
#pragma unroll
        for (int c = 0; c < CCH; c++) s += wx2b[c] * wx2b[c];
        g_prm.c[1] = s;
    }
}

// ---------------- sp_pre ----------------
__global__ void sp_pre_kernel(const float* __restrict__ sp_fea, const float* __restrict__ sp_xyz,
                              const float* __restrict__ wf1w, const float* __restrict__ wx1w,
                              const float* __restrict__ wfg,  const float* __restrict__ wfv,
                              const float* __restrict__ wxg,  const float* __restrict__ wxv) {
    int t = blockIdx.x * blockDim.x + threadIdx.x;   // 65536: (m, i)
    int m = t >> 4, i = t & 15;
    float af = __ldg(wfg + i) * rsqrtf(__ldg(wfv + i) + BN_EPS);
    float ax = __ldg(wxg + i) * rsqrtf(__ldg(wxv + i) + BN_EPS);
    float s = 0.f;
    const float4* fr = reinterpret_cast<const float4*>(sp_fea + m * CCH);
    const float4* wr = reinterpret_cast<const float4*>(wf1w + i * CCH);
#pragma unroll
    for (int c4 = 0; c4 < 8; c4++) {
        float4 a = fr[c4], b = wr[c4];
        s += a.x * b.x + a.y * b.y + a.z * b.z + a.w * b.w;
    }
    g_sph[m * 32 + i] = af * s;
    g_sph[m * 32 + 16 + i] =
        ax * (__ldg(sp_xyz + m * 3 + 0) * __ldg(wx1w + i * 3 + 0)
            + __ldg(sp_xyz + m * 3 + 1) * __ldg(wx1w + i * 3 + 1)
            + __ldg(sp_xyz + m * 3 + 2) * __ldg(wx1w + i * 3 + 2));
    float4* pacc = reinterpret_cast<float4*>(&g_acc[0][0]);
    const int tot4 = RREP * MSEG * ACCW / 4;
    float4 z = make_float4(0.f, 0.f, 0.f, 0.f);
    for (int j = t; j < tot4; j += 65536) pacc[j] = z;
}

// ---------------- prep kernel (f32x2 packed) ----------------
struct __align__(16) SmemP {
    unsigned long long m1p[(CCH / 2) * CCH];
    unsigned long long m2p[(CCH / 2) * CCH];
    unsigned long long wf1p[(MIDD / 2) * CCH];
    unsigned long long wVp[MIDD * CCH];
    unsigned long long wbp[CCH];
    float wx1s[MIDD * 3];
    float am[CCH], bm[CCH], m2b[CCH];
    float betf[MIDD], betx[MIDD], af[MIDD];
};

__global__ void __launch_bounds__(128, 4) prep_kernel(
    const float* __restrict__ o_p_fea, const float* __restrict__ p_xyz,
    const float* __restrict__ wf1w, const float* __restrict__ wf1b,
    const float* __restrict__ wfg,  const float* __restrict__ wfb,
    const float* __restrict__ wfm,  const float* __restrict__ wfv,
    const float* __restrict__ wf2w, const float* __restrict__ wf2b,
    const float* __restrict__ wx1w, const float* __restrict__ wx1b,
    const float* __restrict__ wxg,  const float* __restrict__ wxb,
    const float* __restrict__ wxm,  const float* __restrict__ wxv,
    const float* __restrict__ wx2w, const float* __restrict__ wx2b,
    const float* __restrict__ m1w,  const float* __restrict__ m1b,
    const float* __restrict__ mg,   const float* __restrict__ mbb,
    const float* __restrict__ mm,   const float* __restrict__ mv,
    const float* __restrict__ m2w,  const float* __restrict__ m2b)
{
    __shared__ SmemP sm;
    const int tid = threadIdx.x;

    if (tid < MIDD) {
        float a = wfg[tid] * rsqrtf(wfv[tid] + BN_EPS);
        sm.af[tid] = a;
        sm.betf[tid] = a * (wf1b[tid] - wfm[tid]) + wfb[tid];
        float a2 = wxg[tid] * rsqrtf(wxv[tid] + BN_EPS);
        sm.betx[tid] = a2 * (wx1b[tid] - wxm[tid]) + wxb[tid];
        sm.wx1s[tid * 3 + 0] = a2 * wx1w[tid * 3 + 0];
        sm.wx1s[tid * 3 + 1] = a2 * wx1w[tid * 3 + 1];
        sm.wx1s[tid * 3 + 2] = a2 * wx1w[tid * 3 + 2];
    }
    if (tid < CCH) {
        float a = mg[tid] * rsqrtf(mv[tid] + BN_EPS);
        sm.am[tid] = a;
        sm.bm[tid] = a * (m1b[tid] - mm[tid]) + mbb[tid];
        sm.m2b[tid] = m2b[tid];
    }
    __syncthreads();

    for (int t = tid; t < (CCH / 2) * CCH; t += 128) {
        int cp = t >> 5, j = t & 31;
        sm.m1p[t] = pk2(m1w[(2 * cp) * CCH + j], m1w[(2 * cp + 1) * CCH + j]);
        sm.m2p[t] = pk2(m2w[(2 * cp) * CCH + j], m2w[(2 * cp + 1) * CCH + j]);
    }
    for (int t = tid; t < (MIDD / 2) * CCH; t += 128) {
        int ip = t >> 5, j = t & 31;
        sm.wf1p[t] = pk2(sm.af[2 * ip] * wf1w[(2 * ip) * CCH + j],
                         sm.af[2 * ip + 1] * wf1w[(2 * ip + 1) * CCH + j]);
    }
    for (int t = tid; t < MIDD * CCH; t += 128) {
        int i = t >> 5, c = t & 31;
        sm.wVp[t] = pk2(wf2w[c * MIDD + i], wx2w[c * MIDD + i]);
    }
    if (tid < CCH) sm.wbp[tid] = pk2(wf2b[tid], wx2b[tid]);
    __syncthreads();

    const int n = blockIdx.x * 128 + tid;

    unsigned long long p0d[CCH];
    {
        const float4* pin = reinterpret_cast<const float4*>(o_p_fea + (size_t)n * CCH);
#pragma unroll
        for (int c4 = 0; c4 < 8; c4++) {
            float4 v = pin[c4];
            p0d[c4 * 4 + 0] = pk2(v.x, v.x);
            p0d[c4 * 4 + 1] = pk2(v.y, v.y);
            p0d[c4 * 4 + 2] = pk2(v.z, v.z);
            p0d[c4 * 4 + 3] = pk2(v.w, v.w);
        }
    }

    // BF -> plane 4..7 row 2n
    {
        float BF[MIDD];
#pragma unroll
        for (int ip = 0; ip < MIDD / 2; ip++) {
            unsigned long long acc = 0ull;
            const ulonglong2* wrow = reinterpret_cast<const ulonglong2*>(sm.wf1p + ip * CCH);
#pragma unroll
            for (int j2 = 0; j2 < CCH / 2; j2++) {
                ulonglong2 w = wrow[j2];
                acc = fma2(w.x, p0d[2 * j2], acc);
                acc = fma2(w.y, p0d[2 * j2 + 1], acc);
            }
            float s0, s1; upk2(acc, s0, s1);
            BF[2 * ip]     = sm.betf[2 * ip]     - s0;
            BF[2 * ip + 1] = sm.betf[2 * ip + 1] - s1;
        }
#pragma unroll
        for (int i4 = 0; i4 < 4; i4++)
            g_pv[4 + i4][2 * n] = make_float4(BF[i4 * 4], BF[i4 * 4 + 1], BF[i4 * 4 + 2], BF[i4 * 4 + 3]);
    }
    // BX -> plane 4..7 row 2n+1
    {
        float x0 = p_xyz[(size_t)n * 3 + 0];
        float x1 = p_xyz[(size_t)n * 3 + 1];
        float x2 = p_xyz[(size_t)n * 3 + 2];
        float BX[MIDD];
#pragma unroll
        for (int i = 0; i < MIDD; i++)
            BX[i] = sm.betx[i] - (x0 * sm.wx1s[i * 3 + 0] + x1 * sm.wx1s[i * 3 + 1] + x2 * sm.wx1s[i * 3 + 2]);
#pragma unroll
        for (int i4 = 0; i4 < 4; i4++)
            g_pv[4 + i4][2 * n + 1] = make_float4(BX[i4 * 4], BX[i4 * 4 + 1], BX[i4 * 4 + 2], BX[i4 * 4 + 3]);
    }

    float h1[CCH];
#pragma unroll
    for (int cp = 0; cp < CCH / 2; cp++) {
        unsigned long long acc = 0ull;
        const ulonglong2* wrow = reinterpret_cast<const ulonglong2*>(sm.m1p + cp * CCH);
#pragma unroll
        for (int j2 = 0; j2 < CCH / 2; j2++) {
            ulonglong2 w = wrow[j2];
            acc = fma2(w.x, p0d[2 * j2], acc);
            acc = fma2(w.y, p0d[2 * j2 + 1], acc);
        }
        float s0, s1; upk2(acc, s0, s1);
        h1[2 * cp]     = fmaxf(sm.am[2 * cp] * s0 + sm.bm[2 * cp], 0.f);
        h1[2 * cp + 1] = fmaxf(sm.am[2 * cp + 1] * s1 + sm.bm[2 * cp + 1], 0.f);
    }
    unsigned long long h1d[CCH];
#pragma unroll
    for (int j = 0; j < CCH; j++) h1d[j] = pk2(h1[j], h1[j]);

    float pf[CCH]; float ss = 0.f;
#pragma unroll
    for (int cp = 0; cp < CCH / 2; cp++) {
        unsigned long long acc = pk2(sm.m2b[2 * cp], sm.m2b[2 * cp + 1]);
        const ulonglong2* wrow = reinterpret_cast<const ulonglong2*>(sm.m2p + cp * CCH);
#pragma unroll
        for (int j2 = 0; j2 < CCH / 2; j2++) {
            ulonglong2 w = wrow[j2];
            acc = fma2(w.x, h1d[2 * j2], acc);
            acc = fma2(w.y, h1d[2 * j2 + 1], acc);
        }
        float s0, s1; upk2(acc, s0, s1);
        pf[2 * cp] = s0; pf[2 * cp + 1] = s1;
        ss += s0 * s0 + s1 * s1;
    }
    float inv = rsqrtf(fmaxf(ss, 1e-24f));

    unsigned long long pfd[CCH];
#pragma unroll
    for (int j = 0; j < CCH; j++) pfd[j] = pk2(pf[j], pf[j]);

    float Vf[MIDD], Vx[MIDD];
#pragma unroll
    for (int i = 0; i < MIDD; i++) {
        unsigned long long acc = 0ull;
        const ulonglong2* wrow = reinterpret_cast<const ulonglong2*>(sm.wVp + i * CCH);
#pragma unroll
        for (int c2 = 0; c2 < CCH / 2; c2++) {
            ulonglong2 w = wrow[c2];
            acc = fma2(w.x, pfd[2 * c2], acc);
            acc = fma2(w.y, pfd[2 * c2 + 1], acc);
        }
        float vf, vx; upk2(acc, vf, vx);
        Vf[i] = vf * inv; Vx[i] = vx * inv;
    }
#pragma unroll
    for (int i4 = 0; i4 < 4; i4++) {
        g_pv[i4][2 * n]     = make_float4(Vf[i4 * 4], Vf[i4 * 4 + 1], Vf[i4 * 4 + 2], Vf[i4 * 4 + 3]);
        g_pv[i4][2 * n + 1] = make_float4(Vx[i4 * 4], Vx[i4 * 4 + 1], Vx[i4 * 4 + 2], Vx[i4 * 4 + 3]);
    }
    {
        unsigned long long acc = 0ull;
        const ulonglong2* wrow = reinterpret_cast<const ulonglong2*>(sm.wbp);
#pragma unroll
        for (int c2 = 0; c2 < CCH / 2; c2++) {
            ulonglong2 w = wrow[c2];
            acc = fma2(w.x, pfd[2 * c2], acc);
            acc = fma2(w.y, pfd[2 * c2 + 1], acc);
        }
        float pbf, pbx; upk2(acc, pbf, pbx);
        g_pb[2 * n]     = pbf * inv;
        g_pb[2 * n + 1] = pbx * inv;
    }
}

// ---------------- score kernel: 4 threads per point ----------------
// q = path (0 fea / 1 xyz), g = k-group (0: k=0..2, 1: k=3..5)
// shfl_xor 1 -> combine fea*xyz; shfl_xor 2 -> k-group softmax stats.
// Gram: per-path padded 16x16 (upper tri zero), xyz copy at +260 floats
// (+4 banks) so even/odd lanes' float4 broadcasts hit disjoint banks.
#define OX_OFF 260

__global__ void __launch_bounds__(128) score_kernel(
    const float* __restrict__ o_p_fea, const float* __restrict__ p_xyz,
    const int* __restrict__ idx_abs)
{
    __shared__ __align__(16) float sO[OX_OFF + MIDD * MIDD];
    __shared__ float sg2[2 * MIDD];
    __shared__ float sci[2];
    const int tid = threadIdx.x;
    for (int i = tid; i < MIDD * MIDD; i += 128) {
        sO[i]          = g_prm.O[i];
        sO[OX_OFF + i] = g_prm.O[MIDD * MIDD + i];
    }
    if (tid < 2 * MIDD) sg2[tid] = g_prm.g2[tid];
    if (tid < 2) sci[tid] = g_prm.c[tid];
    __syncthreads();

    const int t = blockIdx.x * 128 + tid;   // 4*NPTS threads
    const int n = t >> 2;
    const int q = t & 1;                    // path
    const int g = (t >> 1) & 1;             // k-group

    const float* Oq  = sO + q * OX_OFF;
    const float* g2q = sg2 + q * MIDD;

    const int row = 2 * n + q;
    float V[MIDD], B[MIDD];
#pragma unroll
    for (int i4 = 0; i4 < 4; i4++) {
        float4 a = g_pv[i4][row];
        V[i4 * 4 + 0] = a.x; V[i4 * 4 + 1] = a.y; V[i4 * 4 + 2] = a.z; V[i4 * 4 + 3] = a.w;
        float4 b = g_pv[4 + i4][row];
        B[i4 * 4 + 0] = b.x; B[i4 * 4 + 1] = b.y; B[i4 * 4 + 2] = b.z; B[i4 * 4 + 3] = b.w;
    }
    const float pb = g_pb[row];
    const float cq = sci[q];

    int idxs[3];
#pragma unroll
    for (int j = 0; j < 3; j++) idxs[j] = idx_abs[(size_t)n * KNB + g * 3 + j];

    float s[3];
#pragma unroll
    for (int j = 0; j < 3; j++) {
        const float4* sr = reinterpret_cast<const float4*>(g_sph + (size_t)idxs[j] * 32 + (q << 4));
        float h[MIDD];
#pragma unroll
        for (int i4 = 0; i4 < 4; i4++) {
            float4 a = sr[i4];
            int p = i4 * 4;
            h[p + 0] = fmaxf(a.x + B[p + 0], 0.f);
            h[p + 1] = fmaxf(a.y + B[p + 1], 0.f);
            h[p + 2] = fmaxf(a.z + B[p + 2], 0.f);
            h[p + 3] = fmaxf(a.w + B[p + 3], 0.f);
        }
        float d = pb;
#pragma unroll
        for (int i = 0; i < MIDD; i++) d += h[i] * V[i];
        // triangular-padded quad form: float4 rows, upper triangle zero
        float qq = cq;
#pragma unroll
        for (int i = 0; i < MIDD; i++) {
            const float4* orow = reinterpret_cast<const float4*>(Oq + i * MIDD);
            float tt = g2q[i];
#pragma unroll
            for (int j4 = 0; j4 <= (i >> 2); j4++) {
                float4 w = orow[j4];
                int p = j4 * 4;
                tt += w.x * h[p + 0] + w.y * h[p + 1] + w.z * h[p + 2] + w.w * h[p + 3];
            }
            qq += h[i] * tt;
        }
        float part = d * rsqrtf(fmaxf(qq, 1e-24f));
        float other = __shfl_xor_sync(0xFFFFFFFFu, part, 1);
        s[j] = part * other;
    }

    // softmax over all 6 via cross-group exchange
    float m_loc = fmaxf(s[0], fmaxf(s[1], s[2]));
    float m_oth = __shfl_xor_sync(0xFFFFFFFFu, m_loc, 2);
    float mx = fmaxf(m_loc, m_oth);
    float e0 = __expf(s[0] - mx);
    float e1 = __expf(s[1] - mx);
    float e2 = __expf(s[2] - mx);
    float e_loc = e0 + e1 + e2;
    float e_oth = __shfl_xor_sync(0xFFFFFFFFu, e_loc, 2);
    float isum = 1.f / (e_loc + e_oth);
    float w0 = e0 * isum, w1 = e1 * isum, w2 = e2 * isum;

    // scatter: this lane handles its 3 ks, its fea-half; odd-q lanes also xyz/wsum
    float p0h[MIDD];
    {
        const float4* pin = reinterpret_cast<const float4*>(o_p_fea + (size_t)n * CCH + (q << 4));
#pragma unroll
        for (int c4 = 0; c4 < 4; c4++) {
            float4 v = pin[c4];
            p0h[c4 * 4 + 0] = v.x; p0h[c4 * 4 + 1] = v.y;
            p0h[c4 * 4 + 2] = v.z; p0h[c4 * 4 + 3] = v.w;
        }
    }
    float x0 = 0.f, x1 = 0.f, x2 = 0.f;
    if (q) {
        x0 = p_xyz[(size_t)n * 3 + 0];
        x1 = p_xyz[(size_t)n * 3 + 1];
        x2 = p_xyz[(size_t)n * 3 + 2];
    }

    float wks[3] = {w0, w1, w2};
    float* accbase = &g_acc[blockIdx.x & (RREP - 1)][0];
#pragma unroll
    for (int j = 0; j < 3; j++) {
        float wk = wks[j];
        float* base = accbase + (size_t)idxs[j] * ACCW + (q << 4);
#pragma unroll
        for (int c = 0; c < MIDD; c += 4) {
            asm volatile("red.global.add.v4.f32 [%0], {%1,%2,%3,%4};"
                         :: "l"(base + c),
                            "f"(p0h[c] * wk), "f"(p0h[c + 1] * wk),
                            "f"(p0h[c + 2] * wk), "f"(p0h[c + 3] * wk)
                         : "memory");
        }
        if (q) {
            asm volatile("red.global.add.v4.f32 [%0], {%1,%2,%3,%4};"
                         :: "l"(accbase + (size_t)idxs[j] * ACCW + CCH),
                            "f"(x0 * wk), "f"(x1 * wk), "f"(x2 * wk), "f"(wk)
                         : "memory");
        }
    }
}

// ---------------- finalize ----------------
__global__ void finalize_kernel(float* __restrict__ out) {
    int t = blockIdx.x * blockDim.x + threadIdx.x;
    if (t >= MSEG * 9) return;
    int m = t / 9;
    int j = t - m * 9;
    float wsum = 0.f;
#pragma unroll
    for (int r = 0; r < RREP; r++) wsum += g_acc[r][m * ACCW + 35];
    float d = 1.f / (wsum + 1e-8f);
    float4 s = make_float4(0.f, 0.f, 0.f, 0.f);
#pragma unroll
    for (int r = 0; r < RREP; r++) {
        float4 v = *reinterpret_cast<const float4*>(&g_acc[r][m * ACCW + j * 4]);
        s.x += v.x; s.y += v.y; s.z += v.z; s.w += v.w;
    }
    if (j < 8) {
        *reinterpret_cast<float4*>(out + (size_t)m * CCH + j * 4) =
            make_float4(s.x * d, s.y * d, s.z * d, s.w * d);
    } else {
        float* oxyz = out + (size_t)MSEG * CCH + (size_t)m * 3;
        oxyz[0] = s.x * d; oxyz[1] = s.y * d; oxyz[2] = s.z * d;
    }
}

// ---------------- launch ----------------
extern "C" void kernel_launch(void* const* d_in, const int* in_sizes, int n_in,
                              void* d_out, int out_size) {
    (void)in_sizes; (void)n_in; (void)out_size;
    const float* sp_fea  = (const float*)d_in[0];
    const float* sp_xyz  = (const float*)d_in[1];
    const float* o_p_fea = (const float*)d_in[2];
    const float* p_xyz   = (const float*)d_in[3];
    const int*   idx_abs = (const int*)d_in[4];
    const float* wf1w = (const float*)d_in[8];
    const float* wf1b = (const float*)d_in[9];
    const float* wfg  = (const float*)d_in[10];
    const float* wfb  = (const float*)d_in[11];
    const float* wfm  = (const float*)d_in[12];
    const float* wfv  = (const float*)d_in[13];
    const float* wf2w = (const float*)d_in[14];
    const float* wf2b = (const float*)d_in[15];
    const float* wx1w = (const float*)d_in[16];
    const float* wx1b = (const float*)d_in[17];
    const float* wxg  = (const float*)d_in[18];
    const float* wxb  = (const float*)d_in[19];
    const float* wxm  = (const float*)d_in[20];
    const float* wxv  = (const float*)d_in[21];
    const float* wx2w = (const float*)d_in[22];
    const float* wx2b = (const float*)d_in[23];
    const float* m1w  = (const float*)d_in[24];
    const float* m1b  = (const float*)d_in[25];
    const float* mg   = (const float*)d_in[26];
    const float* mbb  = (const float*)d_in[27];
    const float* mm   = (const float*)d_in[28];
    const float* mv   = (const float*)d_in[29];
    const float* m2w  = (const float*)d_in[30];
    const float* m2b  = (const float*)d_in[31];

    setup_kernel<<<1, 256>>>(wf2w, wf2b, wx2w, wx2b);
    sp_pre_kernel<<<256, 256>>>(sp_fea, sp_xyz, wf1w, wx1w, wfg, wfv, wxg, wxv);
    prep_kernel<<<NPTS / 128, 128>>>(
        o_p_fea, p_xyz,
        wf1w, wf1b, wfg, wfb, wfm, wfv, wf2w, wf2b,
        wx1w, wx1b, wxg, wxb, wxm, wxv, wx2w, wx2b,
        m1w, m1b, mg, mbb, mm, mv, m2w, m2b);
    score_kernel<<<4 * NPTS / 128, 128>>>(o_p_fea, p_xyz, idx_abs);
    finalize_kernel<<<(MSEG * 9 + 127) / 128, 128>>>((float*)d_out);
}

// round 16
// speedup vs baseline: 1.0197x; 1.0197x over previous
#include <cuda_runtime.h>
#include <math.h>

#define NPTS 131072
#define MSEG 4096
#define CCH  32
#define MIDD 16
#define KNB  6
#define ACCW 36
#define RREP 8
#define BN_EPS 1e-5f

// ---------------- f32x2 helpers (prep kernel) ----------------
__device__ __forceinline__ unsigned long long pk2(float lo, float hi) {
    unsigned long long r;
    asm("mov.b64 %0, {%1,%2};" : "=l"(r) : "f"(lo), "f"(hi));
    return r;
}
__device__ __forceinline__ void upk2(unsigned long long v, float& lo, float& hi) {
    asm("mov.b64 {%0,%1}, %2;" : "=f"(lo), "=f"(hi) : "l"(v));
}
__device__ __forceinline__ unsigned long long fma2(unsigned long long a, unsigned long long b,
                                                   unsigned long long c) {
    unsigned long long d;
    asm("fma.rn.f32x2 %0, %1, %2, %3;" : "=l"(d) : "l"(a), "l"(b), "l"(c));
    return d;
}

// ---------------- static device scratch ----------------
__device__ __align__(256) float g_sph[MSEG * 2 * MIDD];   // [m][0..15]=af*sphf, [m][16..31]=ax*sphx
__device__ __align__(256) float g_acc[RREP][MSEG * ACCW];
// pair-row layout: row r = 2n+path. planes 0..3 = V, 4..7 = B
__device__ __align__(256) float4 g_pv[8][2 * NPTS];
__device__ __align__(256) float  g_pb[2 * NPTS];

struct Prm {
    float OI[2 * MIDD * MIDD];   // interleaved {Of_half, Ox_half} per (i,j)
    float g2i[2 * MIDD];         // interleaved {2*gf, 2*gx}
    float ci[2];                 // {cf, cx}
};
__device__ Prm g_prm;

// ---------------- sp_pre: superpoint projections + zero acc + Gram setup (block 0) ----------------
__global__ void sp_pre_kernel(const float* __restrict__ sp_fea, const float* __restrict__ sp_xyz,
                              const float* __restrict__ wf1w, const float* __restrict__ wx1w,
                              const float* __restrict__ wfg,  const float* __restrict__ wfv,
                              const float* __restrict__ wxg,  const float* __restrict__ wxv,
                              const float* __restrict__ wf2w, const float* __restrict__ wf2b,
                              const float* __restrict__ wx2w, const float* __restrict__ wx2b) {
    int t = blockIdx.x * blockDim.x + threadIdx.x;   // 65536: (m, i)
    int m = t >> 4, i = t & 15;
    float af = __ldg(wfg + i) * rsqrtf(__ldg(wfv + i) + BN_EPS);
    float ax = __ldg(wxg + i) * rsqrtf(__ldg(wxv + i) + BN_EPS);
    float s = 0.f;
    const float4* fr = reinterpret_cast<const float4*>(sp_fea + m * CCH);
    const float4* wr = reinterpret_cast<const float4*>(wf1w + i * CCH);
#pragma unroll
    for (int c4 = 0; c4 < 8; c4++) {
        float4 a = fr[c4], b = wr[c4];
        s += a.x * b.x + a.y * b.y + a.z * b.z + a.w * b.w;
    }
    g_sph[m * 32 + i] = af * s;
    g_sph[m * 32 + 16 + i] =
        ax * (__ldg(sp_xyz + m * 3 + 0) * __ldg(wx1w + i * 3 + 0)
            + __ldg(sp_xyz + m * 3 + 1) * __ldg(wx1w + i * 3 + 1)
            + __ldg(sp_xyz + m * 3 + 2) * __ldg(wx1w + i * 3 + 2));

    // zero accumulators (grid-stride float4)
    float4* pacc = reinterpret_cast<float4*>(&g_acc[0][0]);
    const int tot4 = RREP * MSEG * ACCW / 4;
    float4 z = make_float4(0.f, 0.f, 0.f, 0.f);
    for (int j = t; j < tot4; j += 65536) pacc[j] = z;

    // block 0: Gram constants (256 threads cover all (i,j))
    if (blockIdx.x == 0) {
        int u = threadIdx.x;   // 0..255
        int gi = u >> 4, gj = u & 15;
        float sf = 0.f, sx = 0.f;
#pragma unroll
        for (int c = 0; c < CCH; c++) {
            sf += wf2w[c * MIDD + gi] * wf2w[c * MIDD + gj];
            sx += wx2w[c * MIDD + gi] * wx2w[c * MIDD + gj];
        }
        g_prm.OI[2 * u + 0] = (gj < gi) ? 2.f * sf : (gj == gi ? sf : 0.f);
        g_prm.OI[2 * u + 1] = (gj < gi) ? 2.f * sx : (gj == gi ? sx : 0.f);
        if (u < MIDD) {
            float s1 = 0.f, s2 = 0.f;
#pragma unroll
            for (int c = 0; c < CCH; c++) {
                s1 += wf2w[c * MIDD + u] * wf2b[c];
                s2 += wx2w[c * MIDD + u] * wx2b[c];
            }
            g_prm.g2i[2 * u + 0] = 2.f * s1;
            g_prm.g2i[2 * u + 1] = 2.f * s2;
        } else if (u == 32) {
            float ss = 0.f;
#pragma unroll
            for (int c = 0; c < CCH; c++) ss += wf2b[c] * wf2b[c];
            g_prm.ci[0] = ss;
        } else if (u == 33) {
            float ss = 0.f;
#pragma unroll
            for (int c = 0; c < CCH; c++) ss += wx2b[c] * wx2b[c];
            g_prm.ci[1] = ss;
        }
    }
}

// ---------------- prep kernel (f32x2 packed) ----------------
struct __align__(16) SmemP {
    unsigned long long m1p[(CCH / 2) * CCH];
    unsigned long long m2p[(CCH / 2) * CCH];
    unsigned long long wf1p[(MIDD / 2) * CCH];
    unsigned long long wVp[MIDD * CCH];
    unsigned long long wbp[CCH];
    float wx1s[MIDD * 3];
    float am[CCH], bm[CCH], m2b[CCH];
    float betf[MIDD], betx[MIDD], af[MIDD];
};

__global__ void __launch_bounds__(128, 4) prep_kernel(
    const float* __restrict__ o_p_fea, const float* __restrict__ p_xyz,
    const float* __restrict__ wf1w, const float* __restrict__ wf1b,
    const float* __restrict__ wfg,  const float* __restrict__ wfb,
    const float* __restrict__ wfm,  const float* __restrict__ wfv,
    const float* __restrict__ wf2w, const float* __restrict__ wf2b,
    const float* __restrict__ wx1w, const float* __restrict__ wx1b,
    const float* __restrict__ wxg,  const float* __restrict__ wxb,
    const float* __restrict__ wxm,  const float* __restrict__ wxv,
    const float* __restrict__ wx2w, const float* __restrict__ wx2b,
    const float* __restrict__ m1w,  const float* __restrict__ m1b,
    const float* __restrict__ mg,   const float* __restrict__ mbb,
    const float* __restrict__ mm,   const float* __restrict__ mv,
    const float* __restrict__ m2w,  const float* __restrict__ m2b)
{
    __shared__ SmemP sm;
    const int tid = threadIdx.x;

    if (tid < MIDD) {
        float a = wfg[tid] * rsqrtf(wfv[tid] + BN_EPS);
        sm.af[tid] = a;
        sm.betf[tid] = a * (wf1b[tid] - wfm[tid]) + wfb[tid];
        float a2 = wxg[tid] * rsqrtf(wxv[tid] + BN_EPS);
        sm.betx[tid] = a2 * (wx1b[tid] - wxm[tid]) + wxb[tid];
        sm.wx1s[tid * 3 + 0] = a2 * wx1w[tid * 3 + 0];
        sm.wx1s[tid * 3 + 1] = a2 * wx1w[tid * 3 + 1];
        sm.wx1s[tid * 3 + 2] = a2 * wx1w[tid * 3 + 2];
    }
    if (tid < CCH) {
        float a = mg[tid] * rsqrtf(mv[tid] + BN_EPS);
        sm.am[tid] = a;
        sm.bm[tid] = a * (m1b[tid] - mm[tid]) + mbb[tid];
        sm.m2b[tid] = m2b[tid];
    }
    __syncthreads();

    for (int t = tid; t < (CCH / 2) * CCH; t += 128) {
        int cp = t >> 5, j = t & 31;
        sm.m1p[t] = pk2(m1w[(2 * cp) * CCH + j], m1w[(2 * cp + 1) * CCH + j]);
        sm.m2p[t] = pk2(m2w[(2 * cp) * CCH + j], m2w[(2 * cp + 1) * CCH + j]);
    }
    for (int t = tid; t < (MIDD / 2) * CCH; t += 128) {
        int ip = t >> 5, j = t & 31;
        sm.wf1p[t] = pk2(sm.af[2 * ip] * wf1w[(2 * ip) * CCH + j],
                         sm.af[2 * ip + 1] * wf1w[(2 * ip + 1) * CCH + j]);
    }
    for (int t = tid; t < MIDD * CCH; t += 128) {
        int i = t >> 5, c = t & 31;
        sm.wVp[t] = pk2(wf2w[c * MIDD + i], wx2w[c * MIDD + i]);
    }
    if (tid < CCH) sm.wbp[tid] = pk2(wf2b[tid], wx2b[tid]);
    __syncthreads();

    const int n = blockIdx.x * 128 + tid;

    unsigned long long p0d[CCH];
    {
        const float4* pin = reinterpret_cast<const float4*>(o_p_fea + (size_t)n * CCH);
#pragma unroll
        for (int c4 = 0; c4 < 8; c4++) {
            float4 v = pin[c4];
            p0d[c4 * 4 + 0] = pk2(v.x, v.x);
            p0d[c4 * 4 + 1] = pk2(v.y, v.y);
            p0d[c4 * 4 + 2] = pk2(v.z, v.z);
            p0d[c4 * 4 + 3] = pk2(v.w, v.w);
        }
    }

    // BF -> plane 4..7 row 2n
    {
        float BF[MIDD];
#pragma unroll
        for (int ip = 0; ip < MIDD / 2; ip++) {
            unsigned long long acc = 0ull;
            const ulonglong2* wrow = reinterpret_cast<const ulonglong2*>(sm.wf1p + ip * CCH);
#pragma unroll
            for (int j2 = 0; j2 < CCH / 2; j2++) {
                ulonglong2 w = wrow[j2];
                acc = fma2(w.x, p0d[2 * j2], acc);
                acc = fma2(w.y, p0d[2 * j2 + 1], acc);
            }
            float s0, s1; upk2(acc, s0, s1);
            BF[2 * ip]     = sm.betf[2 * ip]     - s0;
            BF[2 * ip + 1] = sm.betf[2 * ip + 1] - s1;
        }
#pragma unroll
        for (int i4 = 0; i4 < 4; i4++)
            g_pv[4 + i4][2 * n] = make_float4(BF[i4 * 4], BF[i4 * 4 + 1], BF[i4 * 4 + 2], BF[i4 * 4 + 3]);
    }
    // BX -> plane 4..7 row 2n+1
    {
        float x0 = p_xyz[(size_t)n * 3 + 0];
        float x1 = p_xyz[(size_t)n * 3 + 1];
        float x2 = p_xyz[(size_t)n * 3 + 2];
        float BX[MIDD];
#pragma unroll
        for (int i = 0; i < MIDD; i++)
            BX[i] = sm.betx[i] - (x0 * sm.wx1s[i * 3 + 0] + x1 * sm.wx1s[i * 3 + 1] + x2 * sm.wx1s[i * 3 + 2]);
#pragma unroll
        for (int i4 = 0; i4 < 4; i4++)
            g_pv[4 + i4][2 * n + 1] = make_float4(BX[i4 * 4], BX[i4 * 4 + 1], BX[i4 * 4 + 2], BX[i4 * 4 + 3]);
    }

    float h1[CCH];
#pragma unroll
    for (int cp = 0; cp < CCH / 2; cp++) {
        unsigned long long acc = 0ull;
        const ulonglong2* wrow = reinterpret_cast<const ulonglong2*>(sm.m1p + cp * CCH);
#pragma unroll
        for (int j2 = 0; j2 < CCH / 2; j2++) {
            ulonglong2 w = wrow[j2];
            acc = fma2(w.x, p0d[2 * j2], acc);
            acc = fma2(w.y, p0d[2 * j2 + 1], acc);
        }
        float s0, s1; upk2(acc, s0, s1);
        h1[2 * cp]     = fmaxf(sm.am[2 * cp] * s0 + sm.bm[2 * cp], 0.f);
        h1[2 * cp + 1] = fmaxf(sm.am[2 * cp + 1] * s1 + sm.bm[2 * cp + 1], 0.f);
    }
    unsigned long long h1d[CCH];
#pragma unroll
    for (int j = 0; j < CCH; j++) h1d[j] = pk2(h1[j], h1[j]);

    float pf[CCH]; float ss = 0.f;
#pragma unroll
    for (int cp = 0; cp < CCH / 2; cp++) {
        unsigned long long acc = pk2(sm.m2b[2 * cp], sm.m2b[2 * cp + 1]);
        const ulonglong2* wrow = reinterpret_cast<const ulonglong2*>(sm.m2p + cp * CCH);
#pragma unroll
        for (int j2 = 0; j2 < CCH / 2; j2++) {
            ulonglong2 w = wrow[j2];
            acc = fma2(w.x, h1d[2 * j2], acc);
            acc = fma2(w.y, h1d[2 * j2 + 1], acc);
        }
        float s0, s1; upk2(acc, s0, s1);
        pf[2 * cp] = s0; pf[2 * cp + 1] = s1;
        ss += s0 * s0 + s1 * s1;
    }
    float inv = rsqrtf(fmaxf(ss, 1e-24f));

    unsigned long long pfd[CCH];
#pragma unroll
    for (int j = 0; j < CCH; j++) pfd[j] = pk2(pf[j], pf[j]);

    float Vf[MIDD], Vx[MIDD];
#pragma unroll
    for (int i = 0; i < MIDD; i++) {
        unsigned long long acc = 0ull;
        const ulonglong2* wrow = reinterpret_cast<const ulonglong2*>(sm.wVp + i * CCH);
#pragma unroll
        for (int c2 = 0; c2 < CCH / 2; c2++) {
            ulonglong2 w = wrow[c2];
            acc = fma2(w.x, pfd[2 * c2], acc);
            acc = fma2(w.y, pfd[2 * c2 + 1], acc);
        }
        float vf, vx; upk2(acc, vf, vx);
        Vf[i] = vf * inv; Vx[i] = vx * inv;
    }
#pragma unroll
    for (int i4 = 0; i4 < 4; i4++) {
        g_pv[i4][2 * n]     = make_float4(Vf[i4 * 4], Vf[i4 * 4 + 1], Vf[i4 * 4 + 2], Vf[i4 * 4 + 3]);
        g_pv[i4][2 * n + 1] = make_float4(Vx[i4 * 4], Vx[i4 * 4 + 1], Vx[i4 * 4 + 2], Vx[i4 * 4 + 3]);
    }
    {
        unsigned long long acc = 0ull;
        const ulonglong2* wrow = reinterpret_cast<const ulonglong2*>(sm.wbp);
#pragma unroll
        for (int c2 = 0; c2 < CCH / 2; c2++) {
            ulonglong2 w = wrow[c2];
            acc = fma2(w.x, pfd[2 * c2], acc);
            acc = fma2(w.y, pfd[2 * c2 + 1], acc);
        }
        float pbf, pbx; upk2(acc, pbf, pbx);
        g_pb[2 * n]     = pbf * inv;
        g_pb[2 * n + 1] = pbx * inv;
    }
}

// ---------------- score kernel: 4 threads per point (round-14 proven) ----------------
// q = path (0 fea / 1 xyz), g = k-group (0: k=0..2, 1: k=3..5)
// shfl_xor 1 -> combine fea*xyz; shfl_xor 2 -> k-group softmax stats.
__global__ void __launch_bounds__(128) score_kernel(
    const float* __restrict__ o_p_fea, const float* __restrict__ p_xyz,
    const int* __restrict__ idx_abs)
{
    __shared__ float sOI[2 * MIDD * MIDD];
    __shared__ float sg2[2 * MIDD];
    __shared__ float sci[2];
    const int tid = threadIdx.x;
    for (int i = tid; i < 2 * MIDD * MIDD; i += 128) sOI[i] = g_prm.OI[i];
    if (tid < 2 * MIDD) sg2[tid] = g_prm.g2i[tid];
    if (tid < 2) sci[tid] = g_prm.ci[tid];
    __syncthreads();

    const int t = blockIdx.x * 128 + tid;   // 4*NPTS threads
    const int n = t >> 2;
    const int q = t & 1;                    // path
    const int g = (t >> 1) & 1;             // k-group

    const int row = 2 * n + q;
    float V[MIDD], B[MIDD];
#pragma unroll
    for (int i4 = 0; i4 < 4; i4++) {
        float4 a = g_pv[i4][row];
        V[i4 * 4 + 0] = a.x; V[i4 * 4 + 1] = a.y; V[i4 * 4 + 2] = a.z; V[i4 * 4 + 3] = a.w;
        float4 b = g_pv[4 + i4][row];
        B[i4 * 4 + 0] = b.x; B[i4 * 4 + 1] = b.y; B[i4 * 4 + 2] = b.z; B[i4 * 4 + 3] = b.w;
    }
    const float pb = g_pb[row];
    const float cq = sci[q];

    int idxs[3];
#pragma unroll
    for (int j = 0; j < 3; j++) idxs[j] = idx_abs[(size_t)n * KNB + g * 3 + j];

    float s[3];
#pragma unroll
    for (int j = 0; j < 3; j++) {
        const float4* sr = reinterpret_cast<const float4*>(g_sph + (size_t)idxs[j] * 32 + (q << 4));
        float h[MIDD];
#pragma unroll
        for (int i4 = 0; i4 < 4; i4++) {
            float4 a = sr[i4];
            int p = i4 * 4;
            h[p + 0] = fmaxf(a.x + B[p + 0], 0.f);
            h[p + 1] = fmaxf(a.y + B[p + 1], 0.f);
            h[p + 2] = fmaxf(a.z + B[p + 2], 0.f);
            h[p + 3] = fmaxf(a.w + B[p + 3], 0.f);
        }
        float d = pb;
#pragma unroll
        for (int i = 0; i < MIDD; i++) d += h[i] * V[i];
        float qq = cq;
#pragma unroll
        for (int i = 0; i < MIDD; i++) {
            float tt = sg2[2 * i + q] + sOI[(i * 17) * 2 + q] * h[i];  // diag
#pragma unroll
            for (int jj = 0; jj < i; jj++) tt += sOI[((i << 4) + jj) * 2 + q] * h[jj];
            qq += h[i] * tt;
        }
        float part = d * rsqrtf(fmaxf(qq, 1e-24f));
        float other = __shfl_xor_sync(0xFFFFFFFFu, part, 1);
        s[j] = part * other;
    }

    // softmax over all 6 via cross-group exchange
    float m_loc = fmaxf(s[0], fmaxf(s[1], s[2]));
    float m_oth = __shfl_xor_sync(0xFFFFFFFFu, m_loc, 2);
    float mx = fmaxf(m_loc, m_oth);
    float e0 = __expf(s[0] - mx);
    float e1 = __expf(s[1] - mx);
    float e2 = __expf(s[2] - mx);
    float e_loc = e0 + e1 + e2;
    float e_oth = __shfl_xor_sync(0xFFFFFFFFu, e_loc, 2);
    float isum = 1.f / (e_loc + e_oth);
    float w0 = e0 * isum, w1 = e1 * isum, w2 = e2 * isum;

    // scatter: this lane handles its 3 ks, its fea-half; odd-q lanes also xyz/wsum
    float p0h[MIDD];
    {
        const float4* pin = reinterpret_cast<const float4*>(o_p_fea + (size_t)n * CCH + (q << 4));
#pragma unroll
        for (int c4 = 0; c4 < 4; c4++) {
            float4 v = pin[c4];
            p0h[c4 * 4 + 0] = v.x; p0h[c4 * 4 + 1] = v.y;
            p0h[c4 * 4 + 2] = v.z; p0h[c4 * 4 + 3] = v.w;
        }
    }
    float x0 = 0.f, x1 = 0.f, x2 = 0.f;
    if (q) {
        x0 = p_xyz[(size_t)n * 3 + 0];
        x1 = p_xyz[(size_t)n * 3 + 1];
        x2 = p_xyz[(size_t)n * 3 + 2];
    }

    float wks[3] = {w0, w1, w2};
    float* accbase = &g_acc[blockIdx.x & (RREP - 1)][0];
#pragma unroll
    for (int j = 0; j < 3; j++) {
        float wk = wks[j];
        float* base = accbase + (size_t)idxs[j] * ACCW + (q << 4);
#pragma unroll
        for (int c = 0; c < MIDD; c += 4) {
            asm volatile("red.global.add.v4.f32 [%0], {%1,%2,%3,%4};"
                         :: "l"(base + c),
                            "f"(p0h[c] * wk), "f"(p0h[c + 1] * wk),
                            "f"(p0h[c + 2] * wk), "f"(p0h[c + 3] * wk)
                         : "memory");
        }
        if (q) {
            asm volatile("red.global.add.v4.f32 [%0], {%1,%2,%3,%4};"
                         :: "l"(accbase + (size_t)idxs[j] * ACCW + CCH),
                            "f"(x0 * wk), "f"(x1 * wk), "f"(x2 * wk), "f"(wk)
                         : "memory");
        }
    }
}

// ---------------- finalize ----------------
__global__ void finalize_kernel(float* __restrict__ out) {
    int t = blockIdx.x * blockDim.x + threadIdx.x;
    if (t >= MSEG * 9) return;
    int m = t / 9;
    int j = t - m * 9;
    float wsum = 0.f;
#pragma unroll
    for (int r = 0; r < RREP; r++) wsum += g_acc[r][m * ACCW + 35];
    float d = 1.f / (wsum + 1e-8f);
    float4 s = make_float4(0.f, 0.f, 0.f, 0.f);
#pragma unroll
    for (int r = 0; r < RREP; r++) {
        float4 v = *reinterpret_cast<const float4*>(&g_acc[r][m * ACCW + j * 4]);
        s.x += v.x; s.y += v.y; s.z += v.z; s.w += v.w;
    }
    if (j < 8) {
        *reinterpret_cast<float4*>(out + (size_t)m * CCH + j * 4) =
            make_float4(s.x * d, s.y * d, s.z * d, s.w * d);
    } else {
        float* oxyz = out + (size_t)MSEG * CCH + (size_t)m * 3;
        oxyz[0] = s.x * d; oxyz[1] = s.y * d; oxyz[2] = s.z * d;
    }
}

// ---------------- launch ----------------
extern "C" void kernel_launch(void* const* d_in, const int* in_sizes, int n_in,
                              void* d_out, int out_size) {
    (void)in_sizes; (void)n_in; (void)out_size;
    const float* sp_fea  = (const float*)d_in[0];
    const float* sp_xyz  = (const float*)d_in[1];
    const float* o_p_fea = (const float*)d_in[2];
    const float* p_xyz   = (const float*)d_in[3];
    const int*   idx_abs = (const int*)d_in[4];
    const float* wf1w = (const float*)d_in[8];
    const float* wf1b = (const float*)d_in[9];
    const float* wfg  = (const float*)d_in[10];
    const float* wfb  = (const float*)d_in[11];
    const float* wfm  = (const float*)d_in[12];
    const float* wfv  = (const float*)d_in[13];
    const float* wf2w = (const float*)d_in[14];
    const float* wf2b = (const float*)d_in[15];
    const float* wx1w = (const float*)d_in[16];
    const float* wx1b = (const float*)d_in[17];
    const float* wxg  = (const float*)d_in[18];
    const float* wxb  = (const float*)d_in[19];
    const float* wxm  = (const float*)d_in[20];
    const float* wxv  = (const float*)d_in[21];
    const float* wx2w = (const float*)d_in[22];
    const float* wx2b = (const float*)d_in[23];
    const float* m1w  = (const float*)d_in[24];
    const float* m1b  = (const float*)d_in[25];
    const float* mg   = (const float*)d_in[26];
    const float* mbb  = (const float*)d_in[27];
    const float* mm   = (const float*)d_in[28];
    const float* mv   = (const float*)d_in[29];
    const float* m2w  = (const float*)d_in[30];
    const float* m2b  = (const float*)d_in[31];

    sp_pre_kernel<<<256, 256>>>(sp_fea, sp_xyz, wf1w, wx1w, wfg, wfv, wxg, wxv,
                                wf2w, wf2b, wx2w, wx2b);
    prep_kernel<<<NPTS / 128, 128>>>(
        o_p_fea, p_xyz,
        wf1w, wf1b, wfg, wfb, wfm, wfv, wf2w, wf2b,
        wx1w, wx1b, wxg, wxb, wxm, wxv, wx2w, wx2b,
        m1w, m1b, mg, mbb, mm, mv, m2w, m2b);
    score_kernel<<<4 * NPTS / 128, 128>>>(o_p_fea, p_xyz, idx_abs);
    finalize_kernel<<<(MSEG * 9 + 127) / 128, 128>>>((float*)d_out);
}